// round 15
// baseline (speedup 1.0000x reference)
#include <cuda_runtime.h>
#include <cuda_fp16.h>
#include <math.h>

#define B     64
#define T     512
#define NSTEP 128
#define S     512
#define H2D   512
#define ATT   128
#define NCLS  64
#define GRID  148
#define NTH   512

// ---------------- scratch (static device globals; no allocation) ----------------
__device__ __half g_psi16[B * ATT * T];      // TRANSPOSED fp16: [b][a][tt]
__device__ __half g_h16[B * T * H2D];        // fp16 copy of h
__device__ __half g_Wphi16[ATT * S];
__device__ __half g_Wcd16[NCLS * (S + H2D)];
__device__ float  g_part[16 * 64 * 2048];    // [(slot*64+b)*2048 + row]  (8 MB)
__device__ __half g_h1[B * S];
__device__ __half g_h2[B * S];
__device__ __half g_ctx[B * H2D];
__device__ float  g_c1[B * S];
__device__ float  g_c2[B * S];
__device__ unsigned g_cnt1[8];
__device__ unsigned g_cnt2;
__device__ volatile unsigned g_epoch;

__device__ __forceinline__ float tanh_fast(float v)
{
    float r;
    asm("tanh.approx.f32 %0, %1;" : "=f"(r) : "f"(v));
    return r;
}
__device__ __forceinline__ float sigf(float v) { return 0.5f * tanh_fast(0.5f * v) + 0.5f; }

// -------- two-level grid barrier (148 co-resident CTAs) ------------------------
__device__ __forceinline__ void gbar(unsigned& phase, int cta)
{
    __syncthreads();
    if (threadIdx.x == 0) {
        ++phase;
        __threadfence();
        int grp = cta & 7;
        unsigned gsz = 18u + (grp < 4 ? 1u : 0u);   // 148 = 4*19 + 4*18
        if (atomicAdd(&g_cnt1[grp], 1u) == gsz - 1u) {
            g_cnt1[grp] = 0u;
            __threadfence();
            if (atomicAdd(&g_cnt2, 1u) == 7u) {
                g_cnt2 = 0u;
                __threadfence();
                g_epoch = phase;
            } else {
                while (g_epoch != phase) __nanosleep(32);
            }
        } else {
            while (g_epoch != phase) __nanosleep(32);
        }
        __threadfence();
    }
    __syncthreads();
}

// ---------------- smem ----------------
struct SmAttn {
    __align__(16) float part[16][520];      // 33.3 KB
    __align__(16) float vec[1024];
    __align__(16) float phi[ATT];
    __align__(16) float al[T];
    __align__(16) float red[40];
};
struct SmM {                                 // CTAs 0-63 (+128-147 use .s.a only)
    union { SmAttn a; __align__(16) __half As[64 * 136]; } s;
    __align__(16) __half Hc[128 * 512];      // 128 KB: h16[b][tt*4][:] cache
};
struct SmG {                                 // CTAs 64-127
    __align__(16) __half Wb[128 * 136];      // J4 slice
    __align__(16) __half As[64 * 136];
};
struct SmAll {
    __align__(16) __half Wa[128 * 136];      // J1 (cta<64) / J2 (64-127)
    __align__(16) __half Wc[64 * 136];       // J3 slice (64 rows x K128), all <128
    union { SmG g; SmM m; } u;
};

// -------- tensor-core GEMM: D[64 b][ROWS rows] += A[64 b][KT] * W[ROWS][KT] -----
template<int KT, int ROWS>
__device__ __forceinline__ void mma_gemm(const __half* __restrict__ Wsm,
        __half* __restrict__ Asm, int tid, int rowBase, int slot,
        const __half* __restrict__ z, int koff)
{
    constexpr int PK = KT + 8;
    constexpr int NA = ROWS / 32;            // n-atoms per warp tile

    {
        int b = tid >> 3, kq = (tid & 7) * 16;
        const uint4* src = (const uint4*)(z + b * 512 + koff + kq);
        *(uint4*)&Asm[b * PK + kq]     = src[0];
        *(uint4*)&Asm[b * PK + kq + 8] = src[1];
    }
    __syncthreads();

    int T32 = tid & 31, w = tid >> 5;
    int tq = T32 & 3, tr = T32 >> 2;
    int bBase = (w & 3) * 16;
    int rBase = (w >> 2) * (ROWS / 4);

    float d[NA][4];
#pragma unroll
    for (int i = 0; i < NA; ++i)
#pragma unroll
        for (int j = 0; j < 4; ++j) d[i][j] = 0.f;

    const __half* Arow  = Asm + (bBase + tr) * PK;
    const __half* Arow8 = Arow + 8 * PK;

#pragma unroll
    for (int ks = 0; ks < KT / 16; ++ks) {
        int k0 = ks * 16;
        unsigned a0 = *(const unsigned*)&Arow [k0 + 2 * tq];
        unsigned a1 = *(const unsigned*)&Arow8[k0 + 2 * tq];
        unsigned a2 = *(const unsigned*)&Arow [k0 + 8 + 2 * tq];
        unsigned a3 = *(const unsigned*)&Arow8[k0 + 8 + 2 * tq];
#pragma unroll
        for (int na = 0; na < NA; ++na) {
            const __half* Brow = Wsm + (rBase + na * 8 + tr) * PK;
            unsigned b0 = *(const unsigned*)&Brow[k0 + 2 * tq];
            unsigned b1 = *(const unsigned*)&Brow[k0 + 8 + 2 * tq];
            asm volatile(
                "mma.sync.aligned.m16n8k16.row.col.f32.f16.f16.f32 "
                "{%0,%1,%2,%3}, {%4,%5,%6,%7}, {%8,%9}, {%0,%1,%2,%3};"
                : "+f"(d[na][0]), "+f"(d[na][1]), "+f"(d[na][2]), "+f"(d[na][3])
                : "r"(a0), "r"(a1), "r"(a2), "r"(a3), "r"(b0), "r"(b1));
        }
    }

    int gr0 = rowBase + rBase;
#pragma unroll
    for (int na = 0; na < NA; ++na) {
        int rcol = gr0 + na * 8 + 2 * tq;
        *(float2*)&g_part[(size_t)(slot * 64 + bBase + tr) * 2048 + rcol] =
            make_float2(d[na][0], d[na][1]);
        *(float2*)&g_part[(size_t)(slot * 64 + bBase + tr + 8) * 2048 + rcol] =
            make_float2(d[na][2], d[na][3]);
    }
}

// -------- LSTM0 epilogue WIDE: 128 CTAs = (batch, u-half); slots 0-7 ------------
__device__ __forceinline__ void epi0(int cta, int tid,
        const float* __restrict__ Wih0,
        const float* __restrict__ bih, const float* __restrict__ bhh,
        const int* __restrict__ x, int t)
{
    if (cta >= 128) return;
    int b    = cta & 63;
    int half = cta >> 6;
    int u    = half * 256 + (tid >> 1);
    int sh   = (tid & 1) * 4;
    float pre[4];
#pragma unroll
    for (int g = 0; g < 4; ++g) {
        int row = g * 512 + u;
        float s = 0.f;
#pragma unroll
        for (int sp = 0; sp < 4; ++sp)
            s += g_part[(size_t)((sh + sp) * 64 + b) * 2048 + row];
        pre[g] = s;
    }
#pragma unroll
    for (int g = 0; g < 4; ++g)
        pre[g] += __shfl_xor_sync(0xffffffffu, pre[g], 1);
    if ((tid & 1) == 0) {
        int cls = x[b * NSTEP + t];
#pragma unroll
        for (int g = 0; g < 4; ++g) {
            int row = g * 512 + u;
            pre[g] += bih[row] + bhh[row] + Wih0[(size_t)row * 576 + cls];
        }
        float co = g_c1[b * S + u];
        float cn = sigf(pre[1]) * co + sigf(pre[0]) * tanh_fast(pre[2]);
        float hn = sigf(pre[3]) * tanh_fast(cn);
        g_c1[b * S + u] = cn;
        g_h1[b * S + u] = __float2half_rn(hn);
    }
}

// -------- attn main (CTA 0-63): epi1 + phi + e + softmax + ctx (Hc-assisted) ----
__device__ __forceinline__ void attnM(SmM* mm, int b, int tid,
        const float* __restrict__ bih1, const float* __restrict__ bhh1,
        const float* __restrict__ bphi)
{
    SmAttn* a = &mm->s.a;
    int wid  = tid >> 5;
    int lane = tid & 31;

    // ---- LSTM1 epilogue (slots 8-15: J3 8-11, J4 12-15) ----
    {
        int u = tid;
        float pre[4];
#pragma unroll
        for (int g = 0; g < 4; ++g) {
            int row = g * 512 + u;
            float s = bih1[row] + bhh1[row];
#pragma unroll
            for (int sp = 8; sp < 16; ++sp)
                s += g_part[(size_t)(sp * 64 + b) * 2048 + row];
            pre[g] = s;
        }
        float co = g_c2[b * S + u];
        float cn = sigf(pre[1]) * co + sigf(pre[0]) * tanh_fast(pre[2]);
        float hn = sigf(pre[3]) * tanh_fast(cn);
        g_c2[b * S + u] = cn;
        g_h2[b * S + u] = __float2half_rn(hn);
        a->vec[u] = hn;
    }
    __syncthreads();

    // ---- phi = Wphi16 @ h2 + bphi ----
#pragma unroll
    for (int i = 0; i < 8; ++i) {
        int aa = wid * 8 + i;
        const __half* wr = g_Wphi16 + aa * S;
        float sum = 0.f;
#pragma unroll
        for (int it = 0; it < 2; ++it) {
            int idx = it * 256 + lane * 8;
            uint4 w = *(const uint4*)&wr[idx];
            const __half2* wp = (const __half2*)&w;
            float4 v0 = *(const float4*)&a->vec[idx];
            float4 v1 = *(const float4*)&a->vec[idx + 4];
            float2 f0 = __half22float2(wp[0]);
            float2 f1 = __half22float2(wp[1]);
            float2 f2 = __half22float2(wp[2]);
            float2 f3 = __half22float2(wp[3]);
            sum = fmaf(f0.x, v0.x, sum); sum = fmaf(f0.y, v0.y, sum);
            sum = fmaf(f1.x, v0.z, sum); sum = fmaf(f1.y, v0.w, sum);
            sum = fmaf(f2.x, v1.x, sum); sum = fmaf(f2.y, v1.y, sum);
            sum = fmaf(f3.x, v1.z, sum); sum = fmaf(f3.y, v1.w, sum);
        }
#pragma unroll
        for (int o = 16; o > 0; o >>= 1) sum += __shfl_xor_sync(0xffffffffu, sum, o);
        if (lane == 0) a->phi[aa] = sum + bphi[aa];
    }
    __syncthreads();

    // ---- e[tt] via fp16 transposed psi ----
    {
        int aw = tid >> 6;
        int q  = tid & 63;
        const __half* pb = g_psi16 + ((size_t)b * ATT + aw * 16) * T + q * 8;
        float acc[8];
#pragma unroll
        for (int i = 0; i < 8; ++i) acc[i] = 0.f;
#pragma unroll 4
        for (int ai = 0; ai < 16; ++ai) {
            float pa = a->phi[aw * 16 + ai];
            uint4 u = *(const uint4*)&pb[(size_t)ai * T];
            const __half2* hp = (const __half2*)&u;
#pragma unroll
            for (int j = 0; j < 4; ++j) {
                float2 f = __half22float2(hp[j]);
                acc[j * 2 + 0] = fmaf(pa, f.x, acc[j * 2 + 0]);
                acc[j * 2 + 1] = fmaf(pa, f.y, acc[j * 2 + 1]);
            }
        }
        *(float4*)&a->part[aw][q * 8]     = make_float4(acc[0], acc[1], acc[2], acc[3]);
        *(float4*)&a->part[aw][q * 8 + 4] = make_float4(acc[4], acc[5], acc[6], acc[7]);
    }
    __syncthreads();

    // ---- softmax (warp-parallel combines) ----
    float e = 0.f;
#pragma unroll
    for (int r = 0; r < 8; ++r) e += a->part[r][tid];
    float m = e;
#pragma unroll
    for (int o = 16; o > 0; o >>= 1) m = fmaxf(m, __shfl_xor_sync(0xffffffffu, m, o));
    if (lane == 0) a->red[wid] = m;
    __syncthreads();
    if (wid == 0) {
        float v = (lane < 16) ? a->red[lane] : -3.4e38f;
#pragma unroll
        for (int o = 8; o > 0; o >>= 1) v = fmaxf(v, __shfl_xor_sync(0xffffffffu, v, o));
        if (lane == 0) a->red[16] = v;
    }
    __syncthreads();
    m = a->red[16];
    float ex = __expf(e - m);
    a->al[tid] = ex;
    float ssum = ex;
#pragma unroll
    for (int o = 16; o > 0; o >>= 1) ssum += __shfl_xor_sync(0xffffffffu, ssum, o);
    if (lane == 0) a->red[wid] = ssum;
    __syncthreads();
    if (wid == 0) {
        float v = (lane < 16) ? a->red[lane] : 0.f;
#pragma unroll
        for (int o = 8; o > 0; o >>= 1) v += __shfl_xor_sync(0xffffffffu, v, o);
        if (lane == 0) a->red[17] = 1.f / v;
    }
    __syncthreads();
    float inv = a->red[17];

    // ---- ctx: 16 warps x 32 tt; every 4th tt served from the smem cache --------
    {
        const __half* hb = g_h16 + (size_t)b * T * H2D;
        float acc[16];
#pragma unroll
        for (int i = 0; i < 16; ++i) acc[i] = 0.f;
#pragma unroll 4
        for (int tt = wid * 32; tt < wid * 32 + 32; ++tt) {
            float av = a->al[tt];
            uint4 u0, u1;
            if ((tt & 3) == 0) {
                const __half* hs_ = mm->Hc + (tt >> 2) * 512 + lane * 8;
                u0 = *(const uint4*)hs_;
                u1 = *(const uint4*)(hs_ + 256);
            } else {
                const __half* hg = hb + (size_t)tt * H2D + lane * 8;
                u0 = *(const uint4*)hg;
                u1 = *(const uint4*)(hg + 256);
            }
            const __half2* p0 = (const __half2*)&u0;
            const __half2* p1 = (const __half2*)&u1;
#pragma unroll
            for (int j = 0; j < 4; ++j) {
                float2 f0 = __half22float2(p0[j]);
                float2 f1 = __half22float2(p1[j]);
                acc[j * 2 + 0] = fmaf(av, f0.x, acc[j * 2 + 0]);
                acc[j * 2 + 1] = fmaf(av, f0.y, acc[j * 2 + 1]);
                acc[8 + j * 2 + 0] = fmaf(av, f1.x, acc[8 + j * 2 + 0]);
                acc[8 + j * 2 + 1] = fmaf(av, f1.y, acc[8 + j * 2 + 1]);
            }
        }
#pragma unroll
        for (int j = 0; j < 2; ++j) {
            *(float4*)&a->part[wid][j * 256 + lane * 8]     =
                make_float4(acc[j * 8 + 0], acc[j * 8 + 1], acc[j * 8 + 2], acc[j * 8 + 3]);
            *(float4*)&a->part[wid][j * 256 + lane * 8 + 4] =
                make_float4(acc[j * 8 + 4], acc[j * 8 + 5], acc[j * 8 + 6], acc[j * 8 + 7]);
        }
    }
    __syncthreads();
    {
        float cv = 0.f;
#pragma unroll
        for (int w = 0; w < 16; ++w) cv += a->part[w][tid];
        g_ctx[b * H2D + tid] = __float2half_rn(cv * inv);
    }
    __syncthreads();
}

// -------- proj (CTAs 128-143): class-split output projection --------------------
// CTA p owns 4 classes for ALL 64 batches; Wcd rows staged once in smem.
__device__ __forceinline__ void proj_phase(SmAttn* a, int p, int tid,
        const float* __restrict__ bcd, float* __restrict__ out, int t)
{
    int wid  = tid >> 5;
    int lane = tid & 31;

    __half* wsm = (__half*)&a->part[0][0];   // 4 rows x 1024 halves = 8 KB
    {
        const uint4* src = (const uint4*)(g_Wcd16 + (size_t)(p * 4) * (S + H2D));
        if (tid < 512) ((uint4*)wsm)[tid] = src[tid];
    }
    __syncthreads();

    int cl = wid & 3;                 // class within group
    const __half* wr = wsm + cl * 1024;
    float bval = bcd[p * 4 + cl];

    for (int pass = 0; pass < 16; ++pass) {
        int b = pass * 4 + (wid >> 2);
        const __half* vh2 = g_h2 + b * S;
        const __half* vcx = g_ctx + b * H2D;
        float sum = 0.f;
#pragma unroll
        for (int seg = 0; seg < 2; ++seg) {
            const __half* vv = seg ? vcx : vh2;
            const __half* ww = wr + seg * 512;
            int idx = lane * 16;
            uint4 w0 = *(const uint4*)&ww[idx];
            uint4 w1 = *(const uint4*)&ww[idx + 8];
            uint4 v0 = *(const uint4*)&vv[idx];
            uint4 v1 = *(const uint4*)&vv[idx + 8];
            const __half2* wp0 = (const __half2*)&w0;
            const __half2* wp1 = (const __half2*)&w1;
            const __half2* vp0 = (const __half2*)&v0;
            const __half2* vp1 = (const __half2*)&v1;
#pragma unroll
            for (int j = 0; j < 4; ++j) {
                float2 wf0 = __half22float2(wp0[j]);
                float2 vf0 = __half22float2(vp0[j]);
                float2 wf1 = __half22float2(wp1[j]);
                float2 vf1 = __half22float2(vp1[j]);
                sum = fmaf(wf0.x, vf0.x, sum); sum = fmaf(wf0.y, vf0.y, sum);
                sum = fmaf(wf1.x, vf1.x, sum); sum = fmaf(wf1.y, vf1.y, sum);
            }
        }
#pragma unroll
        for (int o = 16; o > 0; o >>= 1) sum += __shfl_xor_sync(0xffffffffu, sum, o);
        if (lane == 0)
            out[((size_t)b * NSTEP + t) * NCLS + p * 4 + cl] = sum + bval;
    }
    __syncthreads();
}

// ---------------- setup kernels ----------------
__global__ void k_h16(const float* __restrict__ h)
{
    size_t i = ((size_t)blockIdx.x * 256 + threadIdx.x) * 8;
    float4 v0 = *(const float4*)&h[i];
    float4 v1 = *(const float4*)&h[i + 4];
    __half2 o[4];
    o[0] = __floats2half2_rn(v0.x, v0.y);
    o[1] = __floats2half2_rn(v0.z, v0.w);
    o[2] = __floats2half2_rn(v1.x, v1.y);
    o[3] = __floats2half2_rn(v1.z, v1.w);
    *(uint4*)&g_h16[i] = *(uint4*)o;
}

__global__ void k_cvt(const float* __restrict__ Wphi, const float* __restrict__ Wcd)
{
    int i = blockIdx.x * 256 + threadIdx.x;
    g_Wphi16[i] = __float2half_rn(Wphi[i]);
    g_Wcd16[i]  = __float2half_rn(Wcd[i]);
}

// psi precompute -> fp16 transposed [b][a][tt]
__global__ void k_psi(const float* __restrict__ h,
                      const float* __restrict__ Wpsi,
                      const float* __restrict__ bpsi)
{
    __shared__ __align__(16) float hs[32][36];
    __shared__ __align__(16) float ws[128][36];
    int b   = blockIdx.y;
    int t0  = blockIdx.x * 32;
    int tid = threadIdx.x;
    int tg  = tid & 7;
    int ag  = tid >> 3;

    float acc[16];
#pragma unroll
    for (int i = 0; i < 16; ++i) acc[i] = 0.f;

    for (int dc = 0; dc < H2D; dc += 32) {
#pragma unroll
        for (int i = 0; i < 4; ++i) {
            int lin = tid + i * 256;
            int r = lin >> 5, c = lin & 31;
            hs[r][c] = h[((size_t)b * T + t0 + r) * H2D + dc + c];
        }
#pragma unroll
        for (int i = 0; i < 16; ++i) {
            int lin = tid + i * 256;
            int r = lin >> 5, c = lin & 31;
            ws[r][c] = Wpsi[r * H2D + dc + c];
        }
        __syncthreads();
#pragma unroll
        for (int k = 0; k < 32; k += 4) {
            float4 hv[4], wv[4];
#pragma unroll
            for (int j = 0; j < 4; ++j) hv[j] = *(const float4*)&hs[tg * 4 + j][k];
#pragma unroll
            for (int j = 0; j < 4; ++j) wv[j] = *(const float4*)&ws[ag * 4 + j][k];
#pragma unroll
            for (int i = 0; i < 4; ++i)
#pragma unroll
                for (int j = 0; j < 4; ++j) {
                    acc[i * 4 + j] = fmaf(hv[i].x, wv[j].x, acc[i * 4 + j]);
                    acc[i * 4 + j] = fmaf(hv[i].y, wv[j].y, acc[i * 4 + j]);
                    acc[i * 4 + j] = fmaf(hv[i].z, wv[j].z, acc[i * 4 + j]);
                    acc[i * 4 + j] = fmaf(hv[i].w, wv[j].w, acc[i * 4 + j]);
                }
        }
        __syncthreads();
    }
#pragma unroll
    for (int i = 0; i < 4; ++i)
#pragma unroll
        for (int j = 0; j < 4; ++j) {
            int tt = t0 + tg * 4 + i;
            int aa = ag * 4 + j;
            g_psi16[((size_t)b * ATT + aa) * T + tt] = __float2half_rn(acc[i * 4 + j] + bpsi[aa]);
        }
}

// ---------------- persistent mega kernel ----------------
__global__ void __launch_bounds__(NTH, 1) k_mega(
        const int* __restrict__ x, const float* __restrict__ h,
        const float* __restrict__ Wih0, const float* __restrict__ Whh0,
        const float* __restrict__ bih0, const float* __restrict__ bhh0,
        const float* __restrict__ Wih1, const float* __restrict__ Whh1,
        const float* __restrict__ bih1, const float* __restrict__ bhh1,
        const float* __restrict__ bphi, const float* __restrict__ bcd,
        float* __restrict__ out)
{
    extern __shared__ char smraw[];
    SmAll* sm = (SmAll*)smraw;

    int cta = blockIdx.x;
    int tid = threadIdx.x;
    unsigned phase = 0;
    if (tid == 0) phase = g_epoch;

    int c64  = (cta < 64) ? cta : cta - 64;
    int rg4  = c64 >> 2;                     // J1/J2/J4: 16 row-groups x K-split 4
    int sp4  = c64 & 3;
    int rg3  = cta >> 2;                     // J3: 32 row-groups (64 rows) x K-split 4
    int sp3  = cta & 3;

    // half* views for staging per role
    __half* AsG = (cta < 64) ? sm->u.m.s.As : sm->u.g.As;

    // one-time fp16 weight staging
    if (cta < 64) {
        int r = tid >> 2, kq = (tid & 3) * 32;
        const float* src = Wih0 + (size_t)(rg4 * 128 + r) * 576 + 64 + sp4 * 128 + kq;
#pragma unroll
        for (int j = 0; j < 32; ++j)
            sm->Wa[r * 136 + kq + j] = __float2half_rn(src[j]);
    } else if (cta < 128) {
        int r = tid >> 2, kq = (tid & 3) * 32;
        const float* s0 = Whh0 + (size_t)(rg4 * 128 + r) * 512 + sp4 * 128 + kq;
        const float* s1 = Whh1 + (size_t)(rg4 * 128 + r) * 512 + sp4 * 128 + kq;
#pragma unroll
        for (int j = 0; j < 32; ++j) {
            sm->Wa[r * 136 + kq + j]     = __float2half_rn(s0[j]);
            sm->u.g.Wb[r * 136 + kq + j] = __float2half_rn(s1[j]);
        }
    }
    if (cta < 128) {
        // J3 slice: 64 rows x K128
#pragma unroll
        for (int i = 0; i < 16; ++i) {
            int idx = i * 512 + tid;
            int r = idx >> 7, k = idx & 127;
            sm->Wc[r * 136 + k] =
                __float2half_rn(Wih1[(size_t)(rg3 * 64 + r) * 512 + sp3 * 128 + k]);
        }
    }

    // init states + ctx = h[:,0,:]
    if (cta < B) {
        int b = cta;
        g_ctx[b * S + tid] = __float2half_rn(h[(size_t)b * T * H2D + tid]);
        g_h1[b * S + tid]  = __float2half_rn(0.f);
        g_h2[b * S + tid]  = __float2half_rn(0.f);
        g_c1[b * S + tid]  = 0.f;
        g_c2[b * S + tid]  = 0.f;
    }
    // attn CTAs: fill h16 cache (every 4th timestep row) — g_h16 ready (k_h16 ran)
    if (cta < 64) {
        uint4* dst = (uint4*)sm->u.m.Hc;
#pragma unroll 4
        for (int i = tid; i < 8192; i += NTH) {
            int tt4 = i >> 6;
            int d8  = (i & 63) * 8;
            dst[i] = *(const uint4*)(g_h16 + ((size_t)cta * T + tt4 * 4) * H2D + d8);
        }
    }
    gbar(phase, cta);

    for (int t = 0; t < NSTEP; ++t) {
        // P1: attnM[t-1] (0-63) || J2[t] = Whh0 @ h1[t-1] (64-127), slots 4-7
        if (cta >= 64 && cta < 128) {
            mma_gemm<128, 128>(sm->Wa, AsG, tid, rg4 * 128, 4 + sp4, g_h1, sp4 * 128);
        } else if (cta < 64 && t > 0) {
            attnM(&sm->u.m, cta, tid, bih1, bhh1, bphi);
        }
        gbar(phase, cta);

        // P2: J1[t] = Wih0 @ ctx[t-1] (0-63, slots 0-3) || J4[t] = Whh1 @ h2[t-1]
        //     (64-127, slots 12-15)
        if (cta < 64) {
            mma_gemm<128, 128>(sm->Wa, AsG, tid, rg4 * 128, sp4, g_ctx, sp4 * 128);
        } else if (cta < 128) {
            mma_gemm<128, 128>(sm->u.g.Wb, AsG, tid, rg4 * 128, 12 + sp4, g_h2, sp4 * 128);
        }
        gbar(phase, cta);

        // P3: epi0[t] (0-127) || proj[t-1] (128-143)
        if (cta < 128) {
            epi0(cta, tid, Wih0, bih0, bhh0, x, t);
        } else if (cta < 144 && t > 0) {
            proj_phase(&sm->u.m.s.a, cta - 128, tid, bcd, out, t - 1);
        }
        gbar(phase, cta);

        // P4: J3[t] = Wih1 @ h1[t] (0-127, 64-row groups, K-split 4, slots 8-11)
        if (cta < 128) {
            mma_gemm<128, 64>(sm->Wc, AsG, tid, rg3 * 64, 8 + sp3, g_h1, sp3 * 128);
        }
        gbar(phase, cta);
    }

    // tail: final step's attention + projection
    if (cta < 64)
        attnM(&sm->u.m, cta, tid, bih1, bhh1, bphi);
    gbar(phase, cta);
    if (cta >= 128 && cta < 144)
        proj_phase(&sm->u.m.s.a, cta - 128, tid, bcd, out, NSTEP - 1);
}

// ---------------- launcher ----------------
extern "C" void kernel_launch(void* const* d_in, const int* in_sizes, int n_in,
                              void* d_out, int out_size)
{
    const int*   x    = (const int*)d_in[0];
    const float* h    = (const float*)d_in[1];
    const float* Wih0 = (const float*)d_in[2];
    const float* Whh0 = (const float*)d_in[3];
    const float* bih0 = (const float*)d_in[4];
    const float* bhh0 = (const float*)d_in[5];
    const float* Wih1 = (const float*)d_in[6];
    const float* Whh1 = (const float*)d_in[7];
    const float* bih1 = (const float*)d_in[8];
    const float* bhh1 = (const float*)d_in[9];
    const float* Wphi = (const float*)d_in[10];
    const float* bphi = (const float*)d_in[11];
    const float* Wpsi = (const float*)d_in[12];
    const float* bpsi = (const float*)d_in[13];
    const float* Wcd  = (const float*)d_in[14];
    const float* bcd  = (const float*)d_in[15];
    float* out = (float*)d_out;

    static int smem_set = 0;
    if (!smem_set) {
        cudaFuncSetAttribute(k_mega, cudaFuncAttributeMaxDynamicSharedMemorySize,
                             (int)sizeof(SmAll));
        smem_set = 1;
    }

    k_h16<<<(B * T * H2D) / (256 * 8), 256>>>(h);
    k_cvt<<<(ATT * S) / 256, 256>>>(Wphi, Wcd);
    k_psi<<<dim3(T / 32, B), 256>>>(h, Wpsi, bpsi);
    k_mega<<<GRID, NTH, sizeof(SmAll)>>>(x, h, Wih0, Whh0, bih0, bhh0,
                                         Wih1, Whh1, bih1, bhh1,
                                         bphi, bcd, out);
}

// round 16
// speedup vs baseline: 1.3217x; 1.3217x over previous
#include <cuda_runtime.h>
#include <cuda_fp16.h>
#include <math.h>

#define B     64
#define T     512
#define NSTEP 128
#define S     512
#define H2D   512
#define ATT   128
#define NCLS  64
#define GRID  148
#define NTH   512

// ---------------- scratch (static device globals; no allocation) ----------------
__device__ __half g_psi16[B * ATT * T];      // TRANSPOSED fp16: [b][a][tt]
__device__ __half g_h16[B * T * H2D];        // fp16 copy of h
__device__ __half g_Wphi16[ATT * S];
__device__ __half g_Wcd16[NCLS * (S + H2D)];
__device__ float  g_part[16 * 64 * 2048];    // [(slot*64+b)*2048 + row]
__device__ __half g_h1[B * S];
__device__ __half g_h2[B * S];
__device__ __half g_ctx[B * H2D];
__device__ float  g_c1[B * S];
__device__ float  g_c2[B * S];
__device__ unsigned g_h2cnt;                 // producer-consumer counters
__device__ unsigned g_ctxcnt;
__device__ unsigned g_cnt1[8];
__device__ unsigned g_cnt2;
__device__ volatile unsigned g_epoch;

__device__ __forceinline__ float tanh_fast(float v)
{
    float r;
    asm("tanh.approx.f32 %0, %1;" : "=f"(r) : "f"(v));
    return r;
}
__device__ __forceinline__ float sigf(float v) { return 0.5f * tanh_fast(0.5f * v) + 0.5f; }

// -------- two-level grid barrier (148 co-resident CTAs), R11-exact --------------
__device__ __forceinline__ void gbar(unsigned& phase, int cta)
{
    __syncthreads();
    if (threadIdx.x == 0) {
        ++phase;
        __threadfence();
        int grp = cta & 7;
        unsigned gsz = 18u + (grp < 4 ? 1u : 0u);   // 148 = 4*19 + 4*18
        if (atomicAdd(&g_cnt1[grp], 1u) == gsz - 1u) {
            g_cnt1[grp] = 0u;
            __threadfence();
            if (atomicAdd(&g_cnt2, 1u) == 7u) {
                g_cnt2 = 0u;
                __threadfence();
                g_epoch = phase;
            } else {
                while (g_epoch != phase) {}
            }
        } else {
            while (g_epoch != phase) {}
        }
        __threadfence();
    }
    __syncthreads();
}

// -------- lightweight producer wait (tid0 spin on monotone counter) -------------
__device__ __forceinline__ void waitcnt(unsigned* cnt, unsigned target, int tid)
{
    if (tid == 0) {
        while (*(volatile unsigned*)cnt < target) {}
        __threadfence();
    }
    __syncthreads();
}

// ---------------- smem ----------------
struct SmAttn {
    __align__(16) float part[16][520];
    __align__(16) float vec[1024];
    __align__(16) float phi[ATT];
    __align__(16) float al[T];
    __align__(16) float red[40];
};
struct SmAll {
    __align__(16) __half Wc[64 * 136];       // J3 slice (64 rows x K128), CTAs <128
    union {
        struct {                              // CTAs 64-127
            __align__(16) __half W0[128 * 136];   // J1 = Wih0 slice
            __align__(16) __half Wh0[128 * 136];  // J2 = Whh0 slice
            __align__(16) __half Wh1[128 * 136];  // J4 = Whh1 slice
            __align__(16) __half As[64 * 136];
        } g;
        union { SmAttn a; __align__(16) __half As[64 * 136]; } m;  // CTAs 0-63
    } u;
};

// -------- tensor-core GEMM: D[64 b][ROWS rows] += A[64 b][K128] * W[ROWS][K128] -
template<int ROWS>
__device__ __forceinline__ void mma_gemm(const __half* __restrict__ Wsm,
        __half* __restrict__ Asm, int tid, int rowBase, int slot,
        const __half* __restrict__ z, int koff)
{
    constexpr int PK = 136;
    constexpr int NA = ROWS / 32;

    {   // stage activations via L2 (fresh data each step; avoids stale L1)
        int b = tid >> 3, kq = (tid & 7) * 16;
        const uint4* src = (const uint4*)(z + b * 512 + koff + kq);
        *(uint4*)&Asm[b * PK + kq]     = __ldcg(src);
        *(uint4*)&Asm[b * PK + kq + 8] = __ldcg(src + 1);
    }
    __syncthreads();

    int T32 = tid & 31, w = tid >> 5;
    int tq = T32 & 3, tr = T32 >> 2;
    int bBase = (w & 3) * 16;
    int rBase = (w >> 2) * (ROWS / 4);

    float d[NA][4];
#pragma unroll
    for (int i = 0; i < NA; ++i)
#pragma unroll
        for (int j = 0; j < 4; ++j) d[i][j] = 0.f;

    const __half* Arow  = Asm + (bBase + tr) * PK;
    const __half* Arow8 = Arow + 8 * PK;

#pragma unroll
    for (int ks = 0; ks < 8; ++ks) {
        int k0 = ks * 16;
        unsigned a0 = *(const unsigned*)&Arow [k0 + 2 * tq];
        unsigned a1 = *(const unsigned*)&Arow8[k0 + 2 * tq];
        unsigned a2 = *(const unsigned*)&Arow [k0 + 8 + 2 * tq];
        unsigned a3 = *(const unsigned*)&Arow8[k0 + 8 + 2 * tq];
#pragma unroll
        for (int na = 0; na < NA; ++na) {
            const __half* Brow = Wsm + (rBase + na * 8 + tr) * PK;
            unsigned b0 = *(const unsigned*)&Brow[k0 + 2 * tq];
            unsigned b1 = *(const unsigned*)&Brow[k0 + 8 + 2 * tq];
            asm volatile(
                "mma.sync.aligned.m16n8k16.row.col.f32.f16.f16.f32 "
                "{%0,%1,%2,%3}, {%4,%5,%6,%7}, {%8,%9}, {%0,%1,%2,%3};"
                : "+f"(d[na][0]), "+f"(d[na][1]), "+f"(d[na][2]), "+f"(d[na][3])
                : "r"(a0), "r"(a1), "r"(a2), "r"(a3), "r"(b0), "r"(b1));
        }
    }

    int gr0 = rowBase + rBase;
#pragma unroll
    for (int na = 0; na < NA; ++na) {
        int rcol = gr0 + na * 8 + 2 * tq;
        *(float2*)&g_part[(size_t)(slot * 64 + bBase + tr) * 2048 + rcol] =
            make_float2(d[na][0], d[na][1]);
        *(float2*)&g_part[(size_t)(slot * 64 + bBase + tr + 8) * 2048 + rcol] =
            make_float2(d[na][2], d[na][3]);
    }
    __syncthreads();   // allow back-to-back calls reusing Asm
}

// -------- LSTM0 epilogue WIDE: 128 CTAs = (batch, u-half); slots 0-7 ------------
__device__ __forceinline__ void epi0(int cta, int tid,
        const float* __restrict__ Wih0,
        const float* __restrict__ bih, const float* __restrict__ bhh,
        const int* __restrict__ x, int t)
{
    if (cta >= 128) return;
    int b    = cta & 63;
    int half = cta >> 6;
    int u    = half * 256 + (tid >> 1);
    int sh   = (tid & 1) * 4;
    float pre[4];
#pragma unroll
    for (int g = 0; g < 4; ++g) {
        int row = g * 512 + u;
        float s = 0.f;
#pragma unroll
        for (int sp = 0; sp < 4; ++sp)
            s += g_part[(size_t)((sh + sp) * 64 + b) * 2048 + row];
        pre[g] = s;
    }
#pragma unroll
    for (int g = 0; g < 4; ++g)
        pre[g] += __shfl_xor_sync(0xffffffffu, pre[g], 1);
    if ((tid & 1) == 0) {
        int cls = x[b * NSTEP + t];
#pragma unroll
        for (int g = 0; g < 4; ++g) {
            int row = g * 512 + u;
            pre[g] += bih[row] + bhh[row] + Wih0[(size_t)row * 576 + cls];
        }
        float co = g_c1[b * S + u];
        float cn = sigf(pre[1]) * co + sigf(pre[0]) * tanh_fast(pre[2]);
        float hn = sigf(pre[3]) * tanh_fast(cn);
        g_c1[b * S + u] = cn;
        g_h1[b * S + u] = __float2half_rn(hn);
    }
}

// -------- attnM (CTA 0-63): epi1 + publish h2 + phi + e + softmax + ctx + proj --
__device__ __forceinline__ void attnM(SmAttn* a, int b, int tid,
        const float* __restrict__ bih1, const float* __restrict__ bhh1,
        const float* __restrict__ bphi, const float* __restrict__ bcd,
        float* __restrict__ out, int t)
{
    int wid  = tid >> 5;
    int lane = tid & 31;

    // ---- LSTM1 epilogue (slots 8-15: J3 8-11, J4 12-15) ----
    {
        int u = tid;
        float pre[4];
#pragma unroll
        for (int g = 0; g < 4; ++g) {
            int row = g * 512 + u;
            float s = bih1[row] + bhh1[row];
#pragma unroll
            for (int sp = 8; sp < 16; ++sp)
                s += g_part[(size_t)(sp * 64 + b) * 2048 + row];
            pre[g] = s;
        }
        float co = g_c2[b * S + u];
        float cn = sigf(pre[1]) * co + sigf(pre[0]) * tanh_fast(pre[2]);
        float hn = sigf(pre[3]) * tanh_fast(cn);
        g_c2[b * S + u] = cn;
        g_h2[b * S + u] = __float2half_rn(hn);
        a->vec[u] = hn;
    }
    __syncthreads();
    if (tid == 0) { __threadfence(); atomicAdd(&g_h2cnt, 1u); }  // release h2

    // ---- phi = Wphi16 @ h2 + bphi ----
#pragma unroll
    for (int i = 0; i < 8; ++i) {
        int aa = wid * 8 + i;
        const __half* wr = g_Wphi16 + aa * S;
        float sum = 0.f;
#pragma unroll
        for (int it = 0; it < 2; ++it) {
            int idx = it * 256 + lane * 8;
            uint4 w = *(const uint4*)&wr[idx];
            const __half2* wp = (const __half2*)&w;
            float4 v0 = *(const float4*)&a->vec[idx];
            float4 v1 = *(const float4*)&a->vec[idx + 4];
            float2 f0 = __half22float2(wp[0]);
            float2 f1 = __half22float2(wp[1]);
            float2 f2 = __half22float2(wp[2]);
            float2 f3 = __half22float2(wp[3]);
            sum = fmaf(f0.x, v0.x, sum); sum = fmaf(f0.y, v0.y, sum);
            sum = fmaf(f1.x, v0.z, sum); sum = fmaf(f1.y, v0.w, sum);
            sum = fmaf(f2.x, v1.x, sum); sum = fmaf(f2.y, v1.y, sum);
            sum = fmaf(f3.x, v1.z, sum); sum = fmaf(f3.y, v1.w, sum);
        }
#pragma unroll
        for (int o = 16; o > 0; o >>= 1) sum += __shfl_xor_sync(0xffffffffu, sum, o);
        if (lane == 0) a->phi[aa] = sum + bphi[aa];
    }
    __syncthreads();

    // ---- e[tt] via fp16 transposed psi ----
    {
        int aw = tid >> 6;
        int q  = tid & 63;
        const __half* pb = g_psi16 + ((size_t)b * ATT + aw * 16) * T + q * 8;
        float acc[8];
#pragma unroll
        for (int i = 0; i < 8; ++i) acc[i] = 0.f;
#pragma unroll 4
        for (int ai = 0; ai < 16; ++ai) {
            float pa = a->phi[aw * 16 + ai];
            uint4 u = *(const uint4*)&pb[(size_t)ai * T];
            const __half2* hp = (const __half2*)&u;
#pragma unroll
            for (int j = 0; j < 4; ++j) {
                float2 f = __half22float2(hp[j]);
                acc[j * 2 + 0] = fmaf(pa, f.x, acc[j * 2 + 0]);
                acc[j * 2 + 1] = fmaf(pa, f.y, acc[j * 2 + 1]);
            }
        }
        *(float4*)&a->part[aw][q * 8]     = make_float4(acc[0], acc[1], acc[2], acc[3]);
        *(float4*)&a->part[aw][q * 8 + 4] = make_float4(acc[4], acc[5], acc[6], acc[7]);
    }
    __syncthreads();

    // ---- softmax (warp-parallel combines) ----
    float e = 0.f;
#pragma unroll
    for (int r = 0; r < 8; ++r) e += a->part[r][tid];
    float m = e;
#pragma unroll
    for (int o = 16; o > 0; o >>= 1) m = fmaxf(m, __shfl_xor_sync(0xffffffffu, m, o));
    if (lane == 0) a->red[wid] = m;
    __syncthreads();
    if (wid == 0) {
        float v = (lane < 16) ? a->red[lane] : -3.4e38f;
#pragma unroll
        for (int o = 8; o > 0; o >>= 1) v = fmaxf(v, __shfl_xor_sync(0xffffffffu, v, o));
        if (lane == 0) a->red[16] = v;
    }
    __syncthreads();
    m = a->red[16];
    float ex = __expf(e - m);
    a->al[tid] = ex;
    float ssum = ex;
#pragma unroll
    for (int o = 16; o > 0; o >>= 1) ssum += __shfl_xor_sync(0xffffffffu, ssum, o);
    if (lane == 0) a->red[wid] = ssum;
    __syncthreads();
    if (wid == 0) {
        float v = (lane < 16) ? a->red[lane] : 0.f;
#pragma unroll
        for (int o = 8; o > 0; o >>= 1) v += __shfl_xor_sync(0xffffffffu, v, o);
        if (lane == 0) a->red[17] = 1.f / v;
    }
    __syncthreads();
    float inv = a->red[17];

    // ---- ctx: 16 warps x 32 tt, fp16 h stream (R11-exact loop) ----
    {
        const __half* hb = g_h16 + (size_t)b * T * H2D;
        float acc[16];
#pragma unroll
        for (int i = 0; i < 16; ++i) acc[i] = 0.f;
#pragma unroll 4
        for (int tt = wid * 32; tt < wid * 32 + 32; ++tt) {
            float av = a->al[tt];
            const __half* hr = hb + (size_t)tt * H2D + lane * 8;
            uint4 u0 = *(const uint4*)hr;
            uint4 u1 = *(const uint4*)(hr + 256);
            const __half2* p0 = (const __half2*)&u0;
            const __half2* p1 = (const __half2*)&u1;
#pragma unroll
            for (int j = 0; j < 4; ++j) {
                float2 f0 = __half22float2(p0[j]);
                float2 f1 = __half22float2(p1[j]);
                acc[j * 2 + 0] = fmaf(av, f0.x, acc[j * 2 + 0]);
                acc[j * 2 + 1] = fmaf(av, f0.y, acc[j * 2 + 1]);
                acc[8 + j * 2 + 0] = fmaf(av, f1.x, acc[8 + j * 2 + 0]);
                acc[8 + j * 2 + 1] = fmaf(av, f1.y, acc[8 + j * 2 + 1]);
            }
        }
#pragma unroll
        for (int j = 0; j < 2; ++j) {
            *(float4*)&a->part[wid][j * 256 + lane * 8]     =
                make_float4(acc[j * 8 + 0], acc[j * 8 + 1], acc[j * 8 + 2], acc[j * 8 + 3]);
            *(float4*)&a->part[wid][j * 256 + lane * 8 + 4] =
                make_float4(acc[j * 8 + 4], acc[j * 8 + 5], acc[j * 8 + 6], acc[j * 8 + 7]);
        }
    }
    __syncthreads();
    {
        float cv = 0.f;
#pragma unroll
        for (int w = 0; w < 16; ++w) cv += a->part[w][tid];
        cv *= inv;
        a->vec[S + tid] = cv;
        g_ctx[b * H2D + tid] = __float2half_rn(cv);
    }
    __syncthreads();
    if (tid == 0) { __threadfence(); atomicAdd(&g_ctxcnt, 1u); }  // release ctx

    // ---- out = Wcd16 @ [h2; ctx] + bcd ----
#pragma unroll
    for (int i = 0; i < 4; ++i) {
        int c = wid * 4 + i;
        const __half* wr = g_Wcd16 + c * (S + H2D);
        float sum = 0.f;
#pragma unroll
        for (int it = 0; it < 4; ++it) {
            int idx = it * 256 + lane * 8;
            uint4 w = *(const uint4*)&wr[idx];
            const __half2* wp = (const __half2*)&w;
            float4 v0 = *(const float4*)&a->vec[idx];
            float4 v1 = *(const float4*)&a->vec[idx + 4];
            float2 f0 = __half22float2(wp[0]);
            float2 f1 = __half22float2(wp[1]);
            float2 f2 = __half22float2(wp[2]);
            float2 f3 = __half22float2(wp[3]);
            sum = fmaf(f0.x, v0.x, sum); sum = fmaf(f0.y, v0.y, sum);
            sum = fmaf(f1.x, v0.z, sum); sum = fmaf(f1.y, v0.w, sum);
            sum = fmaf(f2.x, v1.x, sum); sum = fmaf(f2.y, v1.y, sum);
            sum = fmaf(f3.x, v1.z, sum); sum = fmaf(f3.y, v1.w, sum);
        }
#pragma unroll
        for (int o = 16; o > 0; o >>= 1) sum += __shfl_xor_sync(0xffffffffu, sum, o);
        if (lane == 0) out[((size_t)b * NSTEP + t) * NCLS + c] = sum + bcd[c];
    }
    __syncthreads();
}

// ---------------- setup kernels ----------------
__global__ void k_h16(const float* __restrict__ h)
{
    size_t i = ((size_t)blockIdx.x * 256 + threadIdx.x) * 8;
    float4 v0 = *(const float4*)&h[i];
    float4 v1 = *(const float4*)&h[i + 4];
    __half2 o[4];
    o[0] = __floats2half2_rn(v0.x, v0.y);
    o[1] = __floats2half2_rn(v0.z, v0.w);
    o[2] = __floats2half2_rn(v1.x, v1.y);
    o[3] = __floats2half2_rn(v1.z, v1.w);
    *(uint4*)&g_h16[i] = *(uint4*)o;
}

__global__ void k_cvt(const float* __restrict__ Wphi, const float* __restrict__ Wcd)
{
    int i = blockIdx.x * 256 + threadIdx.x;
    g_Wphi16[i] = __float2half_rn(Wphi[i]);
    g_Wcd16[i]  = __float2half_rn(Wcd[i]);
}

// psi precompute -> fp16 transposed [b][a][tt]
__global__ void k_psi(const float* __restrict__ h,
                      const float* __restrict__ Wpsi,
                      const float* __restrict__ bpsi)
{
    __shared__ __align__(16) float hs[32][36];
    __shared__ __align__(16) float ws[128][36];
    int b   = blockIdx.y;
    int t0  = blockIdx.x * 32;
    int tid = threadIdx.x;
    int tg  = tid & 7;
    int ag  = tid >> 3;

    float acc[16];
#pragma unroll
    for (int i = 0; i < 16; ++i) acc[i] = 0.f;

    for (int dc = 0; dc < H2D; dc += 32) {
#pragma unroll
        for (int i = 0; i < 4; ++i) {
            int lin = tid + i * 256;
            int r = lin >> 5, c = lin & 31;
            hs[r][c] = h[((size_t)b * T + t0 + r) * H2D + dc + c];
        }
#pragma unroll
        for (int i = 0; i < 16; ++i) {
            int lin = tid + i * 256;
            int r = lin >> 5, c = lin & 31;
            ws[r][c] = Wpsi[r * H2D + dc + c];
        }
        __syncthreads();
#pragma unroll
        for (int k = 0; k < 32; k += 4) {
            float4 hv[4], wv[4];
#pragma unroll
            for (int j = 0; j < 4; ++j) hv[j] = *(const float4*)&hs[tg * 4 + j][k];
#pragma unroll
            for (int j = 0; j < 4; ++j) wv[j] = *(const float4*)&ws[ag * 4 + j][k];
#pragma unroll
            for (int i = 0; i < 4; ++i)
#pragma unroll
                for (int j = 0; j < 4; ++j) {
                    acc[i * 4 + j] = fmaf(hv[i].x, wv[j].x, acc[i * 4 + j]);
                    acc[i * 4 + j] = fmaf(hv[i].y, wv[j].y, acc[i * 4 + j]);
                    acc[i * 4 + j] = fmaf(hv[i].z, wv[j].z, acc[i * 4 + j]);
                    acc[i * 4 + j] = fmaf(hv[i].w, wv[j].w, acc[i * 4 + j]);
                }
        }
        __syncthreads();
    }
#pragma unroll
    for (int i = 0; i < 4; ++i)
#pragma unroll
        for (int j = 0; j < 4; ++j) {
            int tt = t0 + tg * 4 + i;
            int aa = ag * 4 + j;
            g_psi16[((size_t)b * ATT + aa) * T + tt] = __float2half_rn(acc[i * 4 + j] + bpsi[aa]);
        }
}

// ---------------- persistent mega kernel ----------------
__global__ void __launch_bounds__(NTH, 1) k_mega(
        const int* __restrict__ x, const float* __restrict__ h,
        const float* __restrict__ Wih0, const float* __restrict__ Whh0,
        const float* __restrict__ bih0, const float* __restrict__ bhh0,
        const float* __restrict__ Wih1, const float* __restrict__ Whh1,
        const float* __restrict__ bih1, const float* __restrict__ bhh1,
        const float* __restrict__ bphi, const float* __restrict__ bcd,
        float* __restrict__ out)
{
    extern __shared__ char smraw[];
    SmAll* sm = (SmAll*)smraw;

    int cta = blockIdx.x;
    int tid = threadIdx.x;
    unsigned phase = 0;
    if (tid == 0) phase = g_epoch;

    int c64  = (cta < 64) ? cta : cta - 64;
    int rg4  = c64 >> 2;                     // J1/J2/J4: 16 row-groups x K-split 4
    int sp4  = c64 & 3;
    int rg3  = cta >> 2;                     // J3: 32 row-groups (64 rows) x K-split 4
    int sp3  = cta & 3;

    __half* AsP = (cta < 64) ? sm->u.m.As : sm->u.g.As;

    // one-time fp16 weight staging
    if (cta >= 64 && cta < 128) {
        int r = tid >> 2, kq = (tid & 3) * 32;
        const float* s0 = Wih0 + (size_t)(rg4 * 128 + r) * 576 + 64 + sp4 * 128 + kq;
        const float* s1 = Whh0 + (size_t)(rg4 * 128 + r) * 512 + sp4 * 128 + kq;
        const float* s2 = Whh1 + (size_t)(rg4 * 128 + r) * 512 + sp4 * 128 + kq;
#pragma unroll
        for (int j = 0; j < 32; ++j) {
            sm->u.g.W0 [r * 136 + kq + j] = __float2half_rn(s0[j]);
            sm->u.g.Wh0[r * 136 + kq + j] = __float2half_rn(s1[j]);
            sm->u.g.Wh1[r * 136 + kq + j] = __float2half_rn(s2[j]);
        }
    }
    if (cta < 128) {
#pragma unroll
        for (int i = 0; i < 16; ++i) {
            int idx = i * 512 + tid;
            int r = idx >> 7, k = idx & 127;
            sm->Wc[r * 136 + k] =
                __float2half_rn(Wih1[(size_t)(rg3 * 64 + r) * 512 + sp3 * 128 + k]);
        }
    }

    // init states + ctx = h[:,0,:] + counters
    if (cta < B) {
        int b = cta;
        g_ctx[b * S + tid] = __float2half_rn(h[(size_t)b * T * H2D + tid]);
        g_h1[b * S + tid]  = __float2half_rn(0.f);
        g_h2[b * S + tid]  = __float2half_rn(0.f);
        g_c1[b * S + tid]  = 0.f;
        g_c2[b * S + tid]  = 0.f;
    }
    if (cta == 0 && tid == 0) { g_h2cnt = 0u; g_ctxcnt = 0u; }
    gbar(phase, cta);

    for (int t = 0; t < NSTEP; ++t) {
        unsigned tgt = 64u * (unsigned)t;

        // P1: attnM[t-1] (0-63) || J2 -> wait h2 -> J4 -> wait ctx -> J1 (64-127)
        if (cta >= 64 && cta < 128) {
            // J2 = Whh0 @ h1[t-1], slots 4-7
            mma_gemm<128>(sm->u.g.Wh0, AsP, tid, rg4 * 128, 4 + sp4, g_h1, sp4 * 128);
            if (t > 0) waitcnt(&g_h2cnt, tgt, tid);
            // J4 = Whh1 @ h2[t-1], slots 12-15
            mma_gemm<128>(sm->u.g.Wh1, AsP, tid, rg4 * 128, 12 + sp4, g_h2, sp4 * 128);
            if (t > 0) waitcnt(&g_ctxcnt, tgt, tid);
            // J1 = Wih0 @ ctx[t-1], slots 0-3
            mma_gemm<128>(sm->u.g.W0, AsP, tid, rg4 * 128, sp4, g_ctx, sp4 * 128);
        } else if (cta < 64 && t > 0) {
            attnM(&sm->u.m.a, cta, tid, bih1, bhh1, bphi, bcd, out, t - 1);
        }
        gbar(phase, cta);

        // P2: epi0[t] -> h1[t] (0-127)
        epi0(cta, tid, Wih0, bih0, bhh0, x, t);
        gbar(phase, cta);

        // P3: J3[t] = Wih1 @ h1[t] (0-127, 64-row groups, K-split 4, slots 8-11)
        if (cta < 128) {
            mma_gemm<64>(sm->Wc, AsP, tid, rg3 * 64, 8 + sp3, g_h1, sp3 * 128);
        }
        gbar(phase, cta);
    }

    // tail: final step's attention + projection
    if (cta < 64)
        attnM(&sm->u.m.a, cta, tid, bih1, bhh1, bphi, bcd, out, NSTEP - 1);
}

// ---------------- launcher ----------------
extern "C" void kernel_launch(void* const* d_in, const int* in_sizes, int n_in,
                              void* d_out, int out_size)
{
    const int*   x    = (const int*)d_in[0];
    const float* h    = (const float*)d_in[1];
    const float* Wih0 = (const float*)d_in[2];
    const float* Whh0 = (const float*)d_in[3];
    const float* bih0 = (const float*)d_in[4];
    const float* bhh0 = (const float*)d_in[5];
    const float* Wih1 = (const float*)d_in[6];
    const float* Whh1 = (const float*)d_in[7];
    const float* bih1 = (const float*)d_in[8];
    const float* bhh1 = (const float*)d_in[9];
    const float* Wphi = (const float*)d_in[10];
    const float* bphi = (const float*)d_in[11];
    const float* Wpsi = (const float*)d_in[12];
    const float* bpsi = (const float*)d_in[13];
    const float* Wcd  = (const float*)d_in[14];
    const float* bcd  = (const float*)d_in[15];
    float* out = (float*)d_out;

    static int smem_set = 0;
    if (!smem_set) {
        cudaFuncSetAttribute(k_mega, cudaFuncAttributeMaxDynamicSharedMemorySize,
                             (int)sizeof(SmAll));
        smem_set = 1;
    }

    k_h16<<<(B * T * H2D) / (256 * 8), 256>>>(h);
    k_cvt<<<(ATT * S) / 256, 256>>>(Wphi, Wcd);
    k_psi<<<dim3(T / 32, B), 256>>>(h, Wpsi, bpsi);
    k_mega<<<GRID, NTH, sizeof(SmAll)>>>(x, h, Wih0, Whh0, bih0, bhh0,
                                         Wih1, Whh1, bih1, bhh1,
                                         bphi, bcd, out);
}

// round 17
// speedup vs baseline: 1.3526x; 1.0234x over previous
#include <cuda_runtime.h>
#include <cuda_fp16.h>
#include <math.h>

#define B     64
#define T     512
#define NSTEP 128
#define S     512
#define H2D   512
#define ATT   128
#define NCLS  64
#define GRID  148
#define NTH   512

// ---------------- scratch (static device globals; no allocation) ----------------
__device__ __half g_psi16[B * ATT * T];      // TRANSPOSED fp16: [b][a][tt]
__device__ __half g_h16[B * T * H2D];        // fp16 copy of h
__device__ __half g_Wphi16[ATT * S];
__device__ __half g_Wcd16[NCLS * (S + H2D)];
__device__ float  g_part[16 * 64 * 2048];    // [(slot*64+b)*2048 + row]
__device__ __half g_h1[B * S];
__device__ __half g_h2[B * S];
__device__ __half g_ctx[B * H2D];
__device__ float  g_c1[B * S];
__device__ float  g_c2[B * S];
__device__ unsigned g_h2cnt;                 // producer-consumer counters
__device__ unsigned g_ctxcnt;
__device__ unsigned g_j1cnt;
__device__ unsigned g_e0cnt;
__device__ unsigned g_cnt1[8];
__device__ unsigned g_cnt2;
__device__ volatile unsigned g_epoch;

__device__ __forceinline__ float tanh_fast(float v)
{
    float r;
    asm("tanh.approx.f32 %0, %1;" : "=f"(r) : "f"(v));
    return r;
}
__device__ __forceinline__ float sigf(float v) { return 0.5f * tanh_fast(0.5f * v) + 0.5f; }

// -------- two-level grid barrier (148 co-resident CTAs), R11-exact --------------
__device__ __forceinline__ void gbar(unsigned& phase, int cta)
{
    __syncthreads();
    if (threadIdx.x == 0) {
        ++phase;
        __threadfence();
        int grp = cta & 7;
        unsigned gsz = 18u + (grp < 4 ? 1u : 0u);   // 148 = 4*19 + 4*18
        if (atomicAdd(&g_cnt1[grp], 1u) == gsz - 1u) {
            g_cnt1[grp] = 0u;
            __threadfence();
            if (atomicAdd(&g_cnt2, 1u) == 7u) {
                g_cnt2 = 0u;
                __threadfence();
                g_epoch = phase;
            } else {
                while (g_epoch != phase) {}
            }
        } else {
            while (g_epoch != phase) {}
        }
        __threadfence();
    }
    __syncthreads();
}

// -------- lightweight producer sync primitives ----------------------------------
__device__ __forceinline__ void publish(unsigned* cnt, int tid)
{
    __syncthreads();
    if (tid == 0) { __threadfence(); atomicAdd(cnt, 1u); }
}
__device__ __forceinline__ void waitcnt(unsigned* cnt, unsigned target, int tid)
{
    if (tid == 0) {
        while (*(volatile unsigned*)cnt < target) {}
        __threadfence();
    }
    __syncthreads();
}

// ---------------- smem ----------------
struct SmAttn {
    __align__(16) float part[16][520];
    __align__(16) float vec[1024];
    __align__(16) float phi[ATT];
    __align__(16) float al[T];
    __align__(16) float red[40];
};
struct SmAll {
    union {
        struct {                              // CTAs 64-127
            __align__(16) __half W0 [128 * 136];  // J1 = Wih0 slice
            __align__(16) __half Wh0[128 * 136];  // J2 = Whh0 slice
            __align__(16) __half Wh1[128 * 136];  // J4 = Whh1 slice
            __align__(16) __half Wc [128 * 136];  // J3 = Wih1 slice
            __align__(16) __half As[64 * 136];
        } g;
        SmAttn a;                             // CTAs 0-63
    } u;
};

// -------- tensor-core GEMM: D[64 b][128 rows] += A[64 b][K128] * W[128][K128] ---
__device__ __forceinline__ void mma_gemm(const __half* __restrict__ Wsm,
        __half* __restrict__ Asm, int tid, int rowBase, int slot,
        const __half* __restrict__ z, int koff)
{
    constexpr int PK = 136;

    {   // stage activations via L2 (fresh data each step)
        int b = tid >> 3, kq = (tid & 7) * 16;
        const uint4* src = (const uint4*)(z + b * 512 + koff + kq);
        *(uint4*)&Asm[b * PK + kq]     = __ldcg(src);
        *(uint4*)&Asm[b * PK + kq + 8] = __ldcg(src + 1);
    }
    __syncthreads();

    int T32 = tid & 31, w = tid >> 5;
    int tq = T32 & 3, tr = T32 >> 2;
    int bBase = (w & 3) * 16;
    int rBase = (w >> 2) * 32;

    float d[4][4];
#pragma unroll
    for (int i = 0; i < 4; ++i)
#pragma unroll
        for (int j = 0; j < 4; ++j) d[i][j] = 0.f;

    const __half* Arow  = Asm + (bBase + tr) * PK;
    const __half* Arow8 = Arow + 8 * PK;

#pragma unroll
    for (int ks = 0; ks < 8; ++ks) {
        int k0 = ks * 16;
        unsigned a0 = *(const unsigned*)&Arow [k0 + 2 * tq];
        unsigned a1 = *(const unsigned*)&Arow8[k0 + 2 * tq];
        unsigned a2 = *(const unsigned*)&Arow [k0 + 8 + 2 * tq];
        unsigned a3 = *(const unsigned*)&Arow8[k0 + 8 + 2 * tq];
#pragma unroll
        for (int na = 0; na < 4; ++na) {
            const __half* Brow = Wsm + (rBase + na * 8 + tr) * PK;
            unsigned b0 = *(const unsigned*)&Brow[k0 + 2 * tq];
            unsigned b1 = *(const unsigned*)&Brow[k0 + 8 + 2 * tq];
            asm volatile(
                "mma.sync.aligned.m16n8k16.row.col.f32.f16.f16.f32 "
                "{%0,%1,%2,%3}, {%4,%5,%6,%7}, {%8,%9}, {%0,%1,%2,%3};"
                : "+f"(d[na][0]), "+f"(d[na][1]), "+f"(d[na][2]), "+f"(d[na][3])
                : "r"(a0), "r"(a1), "r"(a2), "r"(a3), "r"(b0), "r"(b1));
        }
    }

    int gr0 = rowBase + rBase;
#pragma unroll
    for (int na = 0; na < 4; ++na) {
        int rcol = gr0 + na * 8 + 2 * tq;
        *(float2*)&g_part[(size_t)(slot * 64 + bBase + tr) * 2048 + rcol] =
            make_float2(d[na][0], d[na][1]);
        *(float2*)&g_part[(size_t)(slot * 64 + bBase + tr + 8) * 2048 + rcol] =
            make_float2(d[na][2], d[na][3]);
    }
    __syncthreads();   // allow back-to-back calls reusing Asm
}

// -------- LSTM0 epilogue (per-batch, on GEMM CTAs): slots 0-7 -> h1[t] ----------
__device__ __forceinline__ void epi0_b(int b, int tid,
        const float* __restrict__ Wih0,
        const float* __restrict__ bih, const float* __restrict__ bhh,
        const int* __restrict__ x, int t)
{
    int u = tid;
    float pre[4];
#pragma unroll
    for (int g = 0; g < 4; ++g) {
        int row = g * 512 + u;
        float s = bih[row] + bhh[row];
#pragma unroll
        for (int sp = 0; sp < 8; ++sp)
            s += g_part[(size_t)(sp * 64 + b) * 2048 + row];
        pre[g] = s;
    }
    int cls = x[b * NSTEP + t];
#pragma unroll
    for (int g = 0; g < 4; ++g)
        pre[g] += Wih0[(size_t)(g * 512 + u) * 576 + cls];
    float co = g_c1[b * S + u];
    float cn = sigf(pre[1]) * co + sigf(pre[0]) * tanh_fast(pre[2]);
    float hn = sigf(pre[3]) * tanh_fast(cn);
    g_c1[b * S + u] = cn;
    g_h1[b * S + u] = __float2half_rn(hn);
}

// -------- attnM (CTA 0-63): epi1 + publish h2 + phi + e + softmax + ctx + proj --
__device__ __forceinline__ void attnM(SmAttn* a, int b, int tid,
        const float* __restrict__ bih1, const float* __restrict__ bhh1,
        const float* __restrict__ bphi, const float* __restrict__ bcd,
        float* __restrict__ out, int t)
{
    int wid  = tid >> 5;
    int lane = tid & 31;

    // ---- LSTM1 epilogue (slots 8-15: J3 8-11, J4 12-15) ----
    {
        int u = tid;
        float pre[4];
#pragma unroll
        for (int g = 0; g < 4; ++g) {
            int row = g * 512 + u;
            float s = bih1[row] + bhh1[row];
#pragma unroll
            for (int sp = 8; sp < 16; ++sp)
                s += g_part[(size_t)(sp * 64 + b) * 2048 + row];
            pre[g] = s;
        }
        float co = g_c2[b * S + u];
        float cn = sigf(pre[1]) * co + sigf(pre[0]) * tanh_fast(pre[2]);
        float hn = sigf(pre[3]) * tanh_fast(cn);
        g_c2[b * S + u] = cn;
        g_h2[b * S + u] = __float2half_rn(hn);
        a->vec[u] = hn;
    }
    __syncthreads();
    if (tid == 0) { __threadfence(); atomicAdd(&g_h2cnt, 1u); }  // release h2

    // ---- phi = Wphi16 @ h2 + bphi ----
#pragma unroll
    for (int i = 0; i < 8; ++i) {
        int aa = wid * 8 + i;
        const __half* wr = g_Wphi16 + aa * S;
        float sum = 0.f;
#pragma unroll
        for (int it = 0; it < 2; ++it) {
            int idx = it * 256 + lane * 8;
            uint4 w = *(const uint4*)&wr[idx];
            const __half2* wp = (const __half2*)&w;
            float4 v0 = *(const float4*)&a->vec[idx];
            float4 v1 = *(const float4*)&a->vec[idx + 4];
            float2 f0 = __half22float2(wp[0]);
            float2 f1 = __half22float2(wp[1]);
            float2 f2 = __half22float2(wp[2]);
            float2 f3 = __half22float2(wp[3]);
            sum = fmaf(f0.x, v0.x, sum); sum = fmaf(f0.y, v0.y, sum);
            sum = fmaf(f1.x, v0.z, sum); sum = fmaf(f1.y, v0.w, sum);
            sum = fmaf(f2.x, v1.x, sum); sum = fmaf(f2.y, v1.y, sum);
            sum = fmaf(f3.x, v1.z, sum); sum = fmaf(f3.y, v1.w, sum);
        }
#pragma unroll
        for (int o = 16; o > 0; o >>= 1) sum += __shfl_xor_sync(0xffffffffu, sum, o);
        if (lane == 0) a->phi[aa] = sum + bphi[aa];
    }
    __syncthreads();

    // ---- e[tt] via fp16 transposed psi ----
    {
        int aw = tid >> 6;
        int q  = tid & 63;
        const __half* pb = g_psi16 + ((size_t)b * ATT + aw * 16) * T + q * 8;
        float acc[8];
#pragma unroll
        for (int i = 0; i < 8; ++i) acc[i] = 0.f;
#pragma unroll 4
        for (int ai = 0; ai < 16; ++ai) {
            float pa = a->phi[aw * 16 + ai];
            uint4 u = *(const uint4*)&pb[(size_t)ai * T];
            const __half2* hp = (const __half2*)&u;
#pragma unroll
            for (int j = 0; j < 4; ++j) {
                float2 f = __half22float2(hp[j]);
                acc[j * 2 + 0] = fmaf(pa, f.x, acc[j * 2 + 0]);
                acc[j * 2 + 1] = fmaf(pa, f.y, acc[j * 2 + 1]);
            }
        }
        *(float4*)&a->part[aw][q * 8]     = make_float4(acc[0], acc[1], acc[2], acc[3]);
        *(float4*)&a->part[aw][q * 8 + 4] = make_float4(acc[4], acc[5], acc[6], acc[7]);
    }
    __syncthreads();

    // ---- softmax (warp-parallel combines) ----
    float e = 0.f;
#pragma unroll
    for (int r = 0; r < 8; ++r) e += a->part[r][tid];
    float m = e;
#pragma unroll
    for (int o = 16; o > 0; o >>= 1) m = fmaxf(m, __shfl_xor_sync(0xffffffffu, m, o));
    if (lane == 0) a->red[wid] = m;
    __syncthreads();
    if (wid == 0) {
        float v = (lane < 16) ? a->red[lane] : -3.4e38f;
#pragma unroll
        for (int o = 8; o > 0; o >>= 1) v = fmaxf(v, __shfl_xor_sync(0xffffffffu, v, o));
        if (lane == 0) a->red[16] = v;
    }
    __syncthreads();
    m = a->red[16];
    float ex = __expf(e - m);
    a->al[tid] = ex;
    float ssum = ex;
#pragma unroll
    for (int o = 16; o > 0; o >>= 1) ssum += __shfl_xor_sync(0xffffffffu, ssum, o);
    if (lane == 0) a->red[wid] = ssum;
    __syncthreads();
    if (wid == 0) {
        float v = (lane < 16) ? a->red[lane] : 0.f;
#pragma unroll
        for (int o = 8; o > 0; o >>= 1) v += __shfl_xor_sync(0xffffffffu, v, o);
        if (lane == 0) a->red[17] = 1.f / v;
    }
    __syncthreads();
    float inv = a->red[17];

    // ---- ctx: 16 warps x 32 tt, fp16 h stream ----
    {
        const __half* hb = g_h16 + (size_t)b * T * H2D;
        float acc[16];
#pragma unroll
        for (int i = 0; i < 16; ++i) acc[i] = 0.f;
#pragma unroll 4
        for (int tt = wid * 32; tt < wid * 32 + 32; ++tt) {
            float av = a->al[tt];
            const __half* hr = hb + (size_t)tt * H2D + lane * 8;
            uint4 u0 = *(const uint4*)hr;
            uint4 u1 = *(const uint4*)(hr + 256);
            const __half2* p0 = (const __half2*)&u0;
            const __half2* p1 = (const __half2*)&u1;
#pragma unroll
            for (int j = 0; j < 4; ++j) {
                float2 f0 = __half22float2(p0[j]);
                float2 f1 = __half22float2(p1[j]);
                acc[j * 2 + 0] = fmaf(av, f0.x, acc[j * 2 + 0]);
                acc[j * 2 + 1] = fmaf(av, f0.y, acc[j * 2 + 1]);
                acc[8 + j * 2 + 0] = fmaf(av, f1.x, acc[8 + j * 2 + 0]);
                acc[8 + j * 2 + 1] = fmaf(av, f1.y, acc[8 + j * 2 + 1]);
            }
        }
#pragma unroll
        for (int j = 0; j < 2; ++j) {
            *(float4*)&a->part[wid][j * 256 + lane * 8]     =
                make_float4(acc[j * 8 + 0], acc[j * 8 + 1], acc[j * 8 + 2], acc[j * 8 + 3]);
            *(float4*)&a->part[wid][j * 256 + lane * 8 + 4] =
                make_float4(acc[j * 8 + 4], acc[j * 8 + 5], acc[j * 8 + 6], acc[j * 8 + 7]);
        }
    }
    __syncthreads();
    {
        float cv = 0.f;
#pragma unroll
        for (int w = 0; w < 16; ++w) cv += a->part[w][tid];
        cv *= inv;
        a->vec[S + tid] = cv;
        g_ctx[b * H2D + tid] = __float2half_rn(cv);
    }
    __syncthreads();
    if (tid == 0) { __threadfence(); atomicAdd(&g_ctxcnt, 1u); }  // release ctx

    // ---- out = Wcd16 @ [h2; ctx] + bcd ----
#pragma unroll
    for (int i = 0; i < 4; ++i) {
        int c = wid * 4 + i;
        const __half* wr = g_Wcd16 + c * (S + H2D);
        float sum = 0.f;
#pragma unroll
        for (int it = 0; it < 4; ++it) {
            int idx = it * 256 + lane * 8;
            uint4 w = *(const uint4*)&wr[idx];
            const __half2* wp = (const __half2*)&w;
            float4 v0 = *(const float4*)&a->vec[idx];
            float4 v1 = *(const float4*)&a->vec[idx + 4];
            float2 f0 = __half22float2(wp[0]);
            float2 f1 = __half22float2(wp[1]);
            float2 f2 = __half22float2(wp[2]);
            float2 f3 = __half22float2(wp[3]);
            sum = fmaf(f0.x, v0.x, sum); sum = fmaf(f0.y, v0.y, sum);
            sum = fmaf(f1.x, v0.z, sum); sum = fmaf(f1.y, v0.w, sum);
            sum = fmaf(f2.x, v1.x, sum); sum = fmaf(f2.y, v1.y, sum);
            sum = fmaf(f3.x, v1.z, sum); sum = fmaf(f3.y, v1.w, sum);
        }
#pragma unroll
        for (int o = 16; o > 0; o >>= 1) sum += __shfl_xor_sync(0xffffffffu, sum, o);
        if (lane == 0) out[((size_t)b * NSTEP + t) * NCLS + c] = sum + bcd[c];
    }
    __syncthreads();
}

// ---------------- setup kernels ----------------
__global__ void k_h16(const float* __restrict__ h)
{
    size_t i = ((size_t)blockIdx.x * 256 + threadIdx.x) * 8;
    float4 v0 = *(const float4*)&h[i];
    float4 v1 = *(const float4*)&h[i + 4];
    __half2 o[4];
    o[0] = __floats2half2_rn(v0.x, v0.y);
    o[1] = __floats2half2_rn(v0.z, v0.w);
    o[2] = __floats2half2_rn(v1.x, v1.y);
    o[3] = __floats2half2_rn(v1.z, v1.w);
    *(uint4*)&g_h16[i] = *(uint4*)o;
}

__global__ void k_cvt(const float* __restrict__ Wphi, const float* __restrict__ Wcd)
{
    int i = blockIdx.x * 256 + threadIdx.x;
    g_Wphi16[i] = __float2half_rn(Wphi[i]);
    g_Wcd16[i]  = __float2half_rn(Wcd[i]);
}

// psi precompute -> fp16 transposed [b][a][tt]
__global__ void k_psi(const float* __restrict__ h,
                      const float* __restrict__ Wpsi,
                      const float* __restrict__ bpsi)
{
    __shared__ __align__(16) float hs[32][36];
    __shared__ __align__(16) float ws[128][36];
    int b   = blockIdx.y;
    int t0  = blockIdx.x * 32;
    int tid = threadIdx.x;
    int tg  = tid & 7;
    int ag  = tid >> 3;

    float acc[16];
#pragma unroll
    for (int i = 0; i < 16; ++i) acc[i] = 0.f;

    for (int dc = 0; dc < H2D; dc += 32) {
#pragma unroll
        for (int i = 0; i < 4; ++i) {
            int lin = tid + i * 256;
            int r = lin >> 5, c = lin & 31;
            hs[r][c] = h[((size_t)b * T + t0 + r) * H2D + dc + c];
        }
#pragma unroll
        for (int i = 0; i < 16; ++i) {
            int lin = tid + i * 256;
            int r = lin >> 5, c = lin & 31;
            ws[r][c] = Wpsi[r * H2D + dc + c];
        }
        __syncthreads();
#pragma unroll
        for (int k = 0; k < 32; k += 4) {
            float4 hv[4], wv[4];
#pragma unroll
            for (int j = 0; j < 4; ++j) hv[j] = *(const float4*)&hs[tg * 4 + j][k];
#pragma unroll
            for (int j = 0; j < 4; ++j) wv[j] = *(const float4*)&ws[ag * 4 + j][k];
#pragma unroll
            for (int i = 0; i < 4; ++i)
#pragma unroll
                for (int j = 0; j < 4; ++j) {
                    acc[i * 4 + j] = fmaf(hv[i].x, wv[j].x, acc[i * 4 + j]);
                    acc[i * 4 + j] = fmaf(hv[i].y, wv[j].y, acc[i * 4 + j]);
                    acc[i * 4 + j] = fmaf(hv[i].z, wv[j].z, acc[i * 4 + j]);
                    acc[i * 4 + j] = fmaf(hv[i].w, wv[j].w, acc[i * 4 + j]);
                }
        }
        __syncthreads();
    }
#pragma unroll
    for (int i = 0; i < 4; ++i)
#pragma unroll
        for (int j = 0; j < 4; ++j) {
            int tt = t0 + tg * 4 + i;
            int aa = ag * 4 + j;
            g_psi16[((size_t)b * ATT + aa) * T + tt] = __float2half_rn(acc[i * 4 + j] + bpsi[aa]);
        }
}

// ---------------- persistent mega kernel ----------------
__global__ void __launch_bounds__(NTH, 1) k_mega(
        const int* __restrict__ x, const float* __restrict__ h,
        const float* __restrict__ Wih0, const float* __restrict__ Whh0,
        const float* __restrict__ bih0, const float* __restrict__ bhh0,
        const float* __restrict__ Wih1, const float* __restrict__ Whh1,
        const float* __restrict__ bih1, const float* __restrict__ bhh1,
        const float* __restrict__ bphi, const float* __restrict__ bcd,
        float* __restrict__ out)
{
    extern __shared__ char smraw[];
    SmAll* sm = (SmAll*)smraw;

    int cta = blockIdx.x;
    int tid = threadIdx.x;
    unsigned phase = 0;
    if (tid == 0) phase = g_epoch;

    int c64  = (cta < 64) ? cta : cta - 64;
    int rg4  = c64 >> 2;                     // 16 row-groups x K-split 4
    int sp4  = c64 & 3;

    // one-time fp16 weight staging (GEMM CTAs only)
    if (cta >= 64 && cta < 128) {
        int r = tid >> 2, kq = (tid & 3) * 32;
        const float* s0 = Wih0 + (size_t)(rg4 * 128 + r) * 576 + 64 + sp4 * 128 + kq;
        const float* s1 = Whh0 + (size_t)(rg4 * 128 + r) * 512 + sp4 * 128 + kq;
        const float* s2 = Whh1 + (size_t)(rg4 * 128 + r) * 512 + sp4 * 128 + kq;
        const float* s3 = Wih1 + (size_t)(rg4 * 128 + r) * 512 + sp4 * 128 + kq;
#pragma unroll
        for (int j = 0; j < 32; ++j) {
            sm->u.g.W0 [r * 136 + kq + j] = __float2half_rn(s0[j]);
            sm->u.g.Wh0[r * 136 + kq + j] = __float2half_rn(s1[j]);
            sm->u.g.Wh1[r * 136 + kq + j] = __float2half_rn(s2[j]);
            sm->u.g.Wc [r * 136 + kq + j] = __float2half_rn(s3[j]);
        }
    }

    // init states + ctx = h[:,0,:] + counters
    if (cta < B) {
        int b = cta;
        g_ctx[b * S + tid] = __float2half_rn(h[(size_t)b * T * H2D + tid]);
        g_h1[b * S + tid]  = __float2half_rn(0.f);
        g_h2[b * S + tid]  = __float2half_rn(0.f);
        g_c1[b * S + tid]  = 0.f;
        g_c2[b * S + tid]  = 0.f;
    }
    if (cta == 0 && tid == 0) {
        g_h2cnt = 0u; g_ctxcnt = 0u; g_j1cnt = 0u; g_e0cnt = 0u;
    }
    gbar(phase, cta);

    for (int t = 0; t < NSTEP; ++t) {
        unsigned tgt  = 64u * (unsigned)t;
        unsigned tgt1 = 64u * (unsigned)(t + 1);

        if (cta >= 64 && cta < 128) {
            __half* AsP = sm->u.g.As;
            // J2 = Whh0 @ h1[t-1], slots 4-7
            mma_gemm(sm->u.g.Wh0, AsP, tid, rg4 * 128, 4 + sp4, g_h1, sp4 * 128);
            if (t > 0) waitcnt(&g_h2cnt, tgt, tid);
            // J4 = Whh1 @ h2[t-1], slots 12-15
            mma_gemm(sm->u.g.Wh1, AsP, tid, rg4 * 128, 12 + sp4, g_h2, sp4 * 128);
            if (t > 0) waitcnt(&g_ctxcnt, tgt, tid);
            // J1 = Wih0 @ ctx[t-1], slots 0-3
            mma_gemm(sm->u.g.W0, AsP, tid, rg4 * 128, sp4, g_ctx, sp4 * 128);
            publish(&g_j1cnt, tid);
            waitcnt(&g_j1cnt, tgt1, tid);
            // epi0: this CTA owns batch c64
            epi0_b(c64, tid, Wih0, bih0, bhh0, x, t);
            publish(&g_e0cnt, tid);
            waitcnt(&g_e0cnt, tgt1, tid);
            // J3 = Wih1 @ h1[t], slots 8-11
            mma_gemm(sm->u.g.Wc, AsP, tid, rg4 * 128, 8 + sp4, g_h1, sp4 * 128);
        } else if (cta < 64 && t > 0) {
            attnM(&sm->u.a, cta, tid, bih1, bhh1, bphi, bcd, out, t - 1);
        }
        gbar(phase, cta);
    }

    // tail: final step's attention + projection
    if (cta < 64)
        attnM(&sm->u.a, cta, tid, bih1, bhh1, bphi, bcd, out, NSTEP - 1);
}

// ---------------- launcher ----------------
extern "C" void kernel_launch(void* const* d_in, const int* in_sizes, int n_in,
                              void* d_out, int out_size)
{
    const int*   x    = (const int*)d_in[0];
    const float* h    = (const float*)d_in[1];
    const float* Wih0 = (const float*)d_in[2];
    const float* Whh0 = (const float*)d_in[3];
    const float* bih0 = (const float*)d_in[4];
    const float* bhh0 = (const float*)d_in[5];
    const float* Wih1 = (const float*)d_in[6];
    const float* Whh1 = (const float*)d_in[7];
    const float* bih1 = (const float*)d_in[8];
    const float* bhh1 = (const float*)d_in[9];
    const float* Wphi = (const float*)d_in[10];
    const float* bphi = (const float*)d_in[11];
    const float* Wpsi = (const float*)d_in[12];
    const float* bpsi = (const float*)d_in[13];
    const float* Wcd  = (const float*)d_in[14];
    const float* bcd  = (const float*)d_in[15];
    float* out = (float*)d_out;

    static int smem_set = 0;
    if (!smem_set) {
        cudaFuncSetAttribute(k_mega, cudaFuncAttributeMaxDynamicSharedMemorySize,
                             (int)sizeof(SmAll));
        smem_set = 1;
    }

    k_h16<<<(B * T * H2D) / (256 * 8), 256>>>(h);
    k_cvt<<<(ATT * S) / 256, 256>>>(Wphi, Wcd);
    k_psi<<<dim3(T / 32, B), 256>>>(h, Wpsi, bpsi);
    k_mega<<<GRID, NTH, sizeof(SmAll)>>>(x, h, Wih0, Whh0, bih0, bhh0,
                                         Wih1, Whh1, bih1, bhh1,
                                         bphi, bcd, out);
}